// round 5
// baseline (speedup 1.0000x reference)
#include <cuda_runtime.h>

#define NA 200000
#define NDG 50000
#define NB 8192
#define EPSBN 1e-5f
#define TPD 391           // row tiles per degree = ceil(50000/128)
#define FPB 1563          // fp blocks = ceil(200000/128)
#define AR2 256           // floats per k-row of duplicated A (128 values x 2)

typedef unsigned long long u64;

__device__ __forceinline__ void unpack2(u64 v, float& lo, float& hi) {
    asm("mov.b64 {%0, %1}, %2;" : "=f"(lo), "=f"(hi) : "l"(v));
}
__device__ __forceinline__ u64 ffma2(u64 a, u64 b, u64 c) {
    u64 d; asm("fma.rn.f32x2 %0, %1, %2, %3;" : "=l"(d) : "l"(a), "l"(b), "l"(c)); return d;
}

// ---------------- scratch ----------------
__device__ float g_G[(size_t)NA * 272];
__device__ float g_H[(size_t)NA * 128];
__device__ float g_X[(size_t)NA * 128];
__device__ float g_stats[512];
__device__ float g_sc[256];   // BN scale, per layer (0:128 layer1, 128:256 layer2)
__device__ float g_sh[256];   // BN shift

__global__ void zero_stats_kernel() {
    int i = threadIdx.x;
    if (i < 512) g_stats[i] = 0.f;
}

__global__ void prep_stats_kernel(int statsOff, int scOff) {
    int j = threadIdx.x;   // 128
    float mean = g_stats[statsOff + j] * (1.f / NA);
    float var  = g_stats[statsOff + 128 + j] * (1.f / NA) - mean * mean;
    float r = rsqrtf(var + EPSBN);
    g_sc[scOff + j] = r;
    g_sh[scOff + j] = -mean * r;
}

// ---------------- gather: G[row] = [ bn(self) | sum bn(atom-nbrs) | sum bond-nbrs ] ----
// NORM: apply relu(x*sc+sh) to every Hin element BEFORE summing (matches reference)
template <int KIN, bool NORM>
__global__ void gather_kernel(const float* __restrict__ Hin,
                              const float* __restrict__ bond,
                              const int* __restrict__ a1, const int* __restrict__ a2,
                              const int* __restrict__ a3, const int* __restrict__ a4,
                              const int* __restrict__ b1, const int* __restrict__ b2,
                              const int* __restrict__ b3, const int* __restrict__ b4,
                              int scOff) {
    constexpr int CK  = 2 * KIN + 16;
    constexpr int CK4 = CK / 4;
    long long idx = (long long)blockIdx.x * blockDim.x + threadIdx.x;
    if (idx >= (long long)NA * CK4) return;
    int row = (int)(idx / CK4);
    int c4  = (int)(idx - (long long)row * CK4);
    int d   = row / NDG;
    int r   = row - d * NDG;
    int deg = d + 1;
    const int* aidx; const int* bidx;
    if (d == 0)      { aidx = a1; bidx = b1; }
    else if (d == 1) { aidx = a2; bidx = b2; }
    else if (d == 2) { aidx = a3; bidx = b3; }
    else             { aidx = a4; bidx = b4; }
    int c = c4 * 4;
    float4 out;
    if (c < KIN) {
        float4 v = *(const float4*)(Hin + (size_t)row * KIN + c);
        if (NORM) {
            float4 sc4 = *(const float4*)&g_sc[scOff + c];
            float4 sh4 = *(const float4*)&g_sh[scOff + c];
            v.x = fmaxf(0.f, fmaf(v.x, sc4.x, sh4.x));
            v.y = fmaxf(0.f, fmaf(v.y, sc4.y, sh4.y));
            v.z = fmaxf(0.f, fmaf(v.z, sc4.z, sh4.z));
            v.w = fmaxf(0.f, fmaf(v.w, sc4.w, sh4.w));
        }
        out = v;
    } else if (c < 2 * KIN) {
        int cc = c - KIN;
        float4 sc4, sh4;
        if (NORM) {
            sc4 = *(const float4*)&g_sc[scOff + cc];
            sh4 = *(const float4*)&g_sh[scOff + cc];
        }
        float4 s = make_float4(0.f, 0.f, 0.f, 0.f);
        #pragma unroll 4
        for (int t = 0; t < deg; t++) {
            int nb = aidx[r * deg + t];
            float4 v = *(const float4*)(Hin + (size_t)nb * KIN + cc);
            if (NORM) {
                v.x = fmaxf(0.f, fmaf(v.x, sc4.x, sh4.x));
                v.y = fmaxf(0.f, fmaf(v.y, sc4.y, sh4.y));
                v.z = fmaxf(0.f, fmaf(v.z, sc4.z, sh4.z));
                v.w = fmaxf(0.f, fmaf(v.w, sc4.w, sh4.w));
            }
            s.x += v.x; s.y += v.y; s.z += v.z; s.w += v.w;
        }
        out = s;
    } else {
        int cc = c - 2 * KIN;
        float4 s = make_float4(0.f, 0.f, 0.f, 0.f);
        #pragma unroll 4
        for (int t = 0; t < deg; t++) {
            int nb = bidx[r * deg + t];
            float4 v = *(const float4*)(bond + (size_t)nb * 16 + cc);
            s.x += v.x; s.y += v.y; s.z += v.z; s.w += v.w;
        }
        out = s;
    }
    *(float4*)(g_G + (size_t)row * CK + c) = out;
}

// ---------------- shared GEMM machinery (dup-A, mov-free f32x2) ----------------
// As2[k][2*row] = As2[k][2*row+1] = a   (u64 pair = ready f32x2 operand)
// Ws[k][col]                            (float pair = ready f32x2 operand)
__device__ __forceinline__ void sts_chunk(float* As2, float* Ws, int tid,
                                          float4 a0, float4 a1, float4 w0, float4 w1) {
    int rl = tid & 127, kk = (tid >> 7) * 8;
    float* base = As2 + 2 * rl;
    float va[8] = {a0.x, a0.y, a0.z, a0.w, a1.x, a1.y, a1.z, a1.w};
    #pragma unroll
    for (int i = 0; i < 8; i++)
        *(float2*)(base + (kk + i) * AR2) = make_float2(va[i], va[i]);
    int f0 = tid, f1 = tid + 256;
    *(float4*)&Ws[(f0 >> 5) * 128 + (f0 & 31) * 4] = w0;
    *(float4*)&Ws[(f1 >> 5) * 128 + (f1 & 31) * 4] = w1;
}

__device__ __forceinline__ void compute_chunk(const float* As2, const float* Ws,
                                              int tx, int ty, u64 acc[8][4]) {
    #pragma unroll 4
    for (int k = 0; k < 16; k++) {
        ulonglong2 A0 = *(const ulonglong2*)&As2[k * AR2 + ty * 16];
        ulonglong2 A1 = *(const ulonglong2*)&As2[k * AR2 + ty * 16 + 4];
        ulonglong2 A2 = *(const ulonglong2*)&As2[k * AR2 + ty * 16 + 8];
        ulonglong2 A3 = *(const ulonglong2*)&As2[k * AR2 + ty * 16 + 12];
        ulonglong2 W0 = *(const ulonglong2*)&Ws[k * 128 + tx * 8];
        ulonglong2 W1 = *(const ulonglong2*)&Ws[k * 128 + tx * 8 + 4];
        u64 aa[8] = {A0.x, A0.y, A1.x, A1.y, A2.x, A2.y, A3.x, A3.y};
        u64 ww[4] = {W0.x, W0.y, W1.x, W1.y};
        #pragma unroll
        for (int i = 0; i < 8; i++) {
            acc[i][0] = ffma2(aa[i], ww[0], acc[i][0]);
            acc[i][1] = ffma2(aa[i], ww[1], acc[i][1]);
            acc[i][2] = ffma2(aa[i], ww[2], acc[i][2]);
            acc[i][3] = ffma2(aa[i], ww[3], acc[i][3]);
        }
    }
}

#define CONV_SMEM ((2 * 16 * AR2 + 2 * 16 * 128) * 4)          // 49152
#define FP_SMEM   ((2 * 16 * AR2 + 2 * 16 * 128 + 256) * 4)    // 50176

// ---------------- conv GEMM: 128x128 tile, 8x8/thread, f32x2, BN-stat epilogue ----
template <int KIN>
__global__ __launch_bounds__(256, 2)
void conv_kernel(const float* __restrict__ selfW,
                 const float* __restrict__ dW1, const float* __restrict__ dW2,
                 const float* __restrict__ dW3, const float* __restrict__ dW4,
                 const float* __restrict__ bias,
                 float* __restrict__ Xout, int statsOff) {
    constexpr int CK  = 2 * KIN + 16;
    constexpr int NCH = CK / 16;
    extern __shared__ float sm[];
    float* As2 = sm;                      // 2 x 16 x AR2
    float* Ws  = sm + 2 * 16 * AR2;       // 2 x 16 x 128

    int tid = threadIdx.x;
    int tx = tid & 15, ty = tid >> 4;
    int d    = blockIdx.x / TPD;
    int tile = blockIdx.x - d * TPD;
    int rowbase = d * NDG + tile * 128;
    int rowend  = min((d + 1) * NDG, rowbase + 128);
    const float* dW = (d == 0) ? dW1 : (d == 1) ? dW2 : (d == 2) ? dW3 : dW4;

    int rl = tid & 127, kk = (tid >> 7) * 8;
    int rg = rowbase + rl;
    bool rvalid = rg < rowend;
    const float* Grow = g_G + (size_t)rg * CK + kk;

    float bcol[8];
    *(float4*)&bcol[0] = *(const float4*)&bias[tx * 8];
    *(float4*)&bcol[4] = *(const float4*)&bias[tx * 8 + 4];

    {
        float4 a0 = make_float4(0,0,0,0), a1 = a0;
        if (rvalid) { a0 = *(const float4*)Grow; a1 = *(const float4*)(Grow + 4); }
        float4 w0 = ((const float4*)selfW)[tid];
        float4 w1 = ((const float4*)selfW)[tid + 256];
        sts_chunk(As2, Ws, tid, a0, a1, w0, w1);
    }
    __syncthreads();

    u64 acc[8][4];
    #pragma unroll
    for (int i = 0; i < 8; i++)
        #pragma unroll
        for (int q = 0; q < 4; q++) acc[i][q] = 0ull;

    for (int c = 0; c < NCH; c++) {
        int buf = c & 1;
        float4 a0, a1, w0, w1;
        bool havenext = (c + 1 < NCH);
        if (havenext) {
            int k0 = (c + 1) * 16;
            a0 = make_float4(0,0,0,0); a1 = a0;
            if (rvalid) { a0 = *(const float4*)(Grow + k0); a1 = *(const float4*)(Grow + k0 + 4); }
            const float* wsrc = (k0 < KIN) ? (selfW + (size_t)k0 * 128)
                                           : (dW + (size_t)(k0 - KIN) * 128);
            w0 = ((const float4*)wsrc)[tid];
            w1 = ((const float4*)wsrc)[tid + 256];
        }
        compute_chunk(As2 + buf * 16 * AR2, Ws + buf * 16 * 128, tx, ty, acc);
        if (havenext) sts_chunk(As2 + (buf ^ 1) * 16 * AR2, Ws + (buf ^ 1) * 16 * 128,
                                tid, a0, a1, w0, w1);
        __syncthreads();
    }

    // epilogue: bias, store, BN partials
    float psum[8], psq[8];
    #pragma unroll
    for (int j = 0; j < 8; j++) { psum[j] = 0.f; psq[j] = 0.f; }
    #pragma unroll
    for (int i = 0; i < 8; i++) {
        int r = rowbase + ty * 8 + i;
        float x[8];
        unpack2(acc[i][0], x[0], x[1]); unpack2(acc[i][1], x[2], x[3]);
        unpack2(acc[i][2], x[4], x[5]); unpack2(acc[i][3], x[6], x[7]);
        #pragma unroll
        for (int j = 0; j < 8; j++) x[j] += bcol[j];
        if (r < rowend) {
            float* outp = Xout + (size_t)r * 128 + tx * 8;
            *(float4*)outp       = make_float4(x[0], x[1], x[2], x[3]);
            *(float4*)(outp + 4) = make_float4(x[4], x[5], x[6], x[7]);
            #pragma unroll
            for (int j = 0; j < 8; j++) { psum[j] += x[j]; psq[j] += x[j] * x[j]; }
        }
    }
    float* redS = As2;            // reuse smem (post-sync)
    float* redQ = As2 + 2048;
    #pragma unroll
    for (int j = 0; j < 8; j++) {
        redS[ty * 128 + tx * 8 + j] = psum[j];
        redQ[ty * 128 + tx * 8 + j] = psq[j];
    }
    __syncthreads();
    if (tid < 128) {
        float s = 0.f, q = 0.f;
        #pragma unroll
        for (int t = 0; t < 16; t++) { s += redS[t * 128 + tid]; q += redQ[t * 128 + tid]; }
        atomicAdd(&g_stats[statsOff + tid], s);
        atomicAdd(&g_stats[statsOff + 128 + tid], q);
    }
}

// ---------------- fp update: GEMM (optional fused BN+relu on input) + softmax + segsum ----
template <int KIN, bool NORM>
__global__ __launch_bounds__(256, 2)
void fp_kernel(const float* __restrict__ Hin,
               const float* __restrict__ W, const float* __restrict__ bias,
               const int* __restrict__ mol_ids,
               float* __restrict__ fp, int scOff) {
    constexpr int NCH = KIN / 16;
    extern __shared__ float sm[];
    float* As2  = sm;
    float* Ws   = sm + 2 * 16 * AR2;
    float* sc_s = Ws + 2 * 16 * 128;    // KIN <= 128
    float* sh_s = sc_s + 128;

    int tid = threadIdx.x;
    int tx = tid & 15, ty = tid >> 4;
    int rowbase = blockIdx.x * 128;

    int rl = tid & 127, kk = (tid >> 7) * 8;
    int rg = rowbase + rl;
    bool rvalid = rg < NA;
    const float* Hrow = Hin + (size_t)rg * KIN + kk;

    float bcol[8];
    *(float4*)&bcol[0] = *(const float4*)&bias[tx * 8];
    *(float4*)&bcol[4] = *(const float4*)&bias[tx * 8 + 4];

    if (NORM) {
        if (tid < KIN) { sc_s[tid] = g_sc[scOff + tid]; sh_s[tid] = g_sh[scOff + tid]; }
        __syncthreads();
    }

    auto bn8 = [&](float4& a0, float4& a1, int c) {
        if (NORM) {
            float4 s0 = *(const float4*)&sc_s[c],     h0 = *(const float4*)&sh_s[c];
            float4 s1 = *(const float4*)&sc_s[c + 4], h1 = *(const float4*)&sh_s[c + 4];
            a0.x = fmaxf(0.f, fmaf(a0.x, s0.x, h0.x));
            a0.y = fmaxf(0.f, fmaf(a0.y, s0.y, h0.y));
            a0.z = fmaxf(0.f, fmaf(a0.z, s0.z, h0.z));
            a0.w = fmaxf(0.f, fmaf(a0.w, s0.w, h0.w));
            a1.x = fmaxf(0.f, fmaf(a1.x, s1.x, h1.x));
            a1.y = fmaxf(0.f, fmaf(a1.y, s1.y, h1.y));
            a1.z = fmaxf(0.f, fmaf(a1.z, s1.z, h1.z));
            a1.w = fmaxf(0.f, fmaf(a1.w, s1.w, h1.w));
        }
    };

    {
        float4 a0 = make_float4(0,0,0,0), a1 = a0;
        if (rvalid) { a0 = *(const float4*)Hrow; a1 = *(const float4*)(Hrow + 4); }
        bn8(a0, a1, kk);
        float4 w0 = ((const float4*)W)[tid];
        float4 w1 = ((const float4*)W)[tid + 256];
        sts_chunk(As2, Ws, tid, a0, a1, w0, w1);
    }
    __syncthreads();

    u64 acc[8][4];
    #pragma unroll
    for (int i = 0; i < 8; i++)
        #pragma unroll
        for (int q = 0; q < 4; q++) acc[i][q] = 0ull;

    for (int c = 0; c < NCH; c++) {
        int buf = c & 1;
        float4 a0, a1, w0, w1;
        bool havenext = (c + 1 < NCH);
        if (havenext) {
            int k0 = (c + 1) * 16;
            a0 = make_float4(0,0,0,0); a1 = a0;
            if (rvalid) { a0 = *(const float4*)(Hrow + k0); a1 = *(const float4*)(Hrow + k0 + 4); }
            bn8(a0, a1, k0 + kk);
            const float* wsrc = W + (size_t)k0 * 128;
            w0 = ((const float4*)wsrc)[tid];
            w1 = ((const float4*)wsrc)[tid + 256];
        }
        compute_chunk(As2 + buf * 16 * AR2, Ws + buf * 16 * 128, tx, ty, acc);
        if (havenext) sts_chunk(As2 + (buf ^ 1) * 16 * AR2, Ws + (buf ^ 1) * 16 * 128,
                                tid, a0, a1, w0, w1);
        __syncthreads();
    }

    int mm[8];
    #pragma unroll
    for (int i = 0; i < 8; i++) {
        int r = rowbase + ty * 8 + i;
        mm[i] = (r < NA) ? mol_ids[r] : -1;
    }

    int cur = -1;
    float run[8];
    #pragma unroll
    for (int i = 0; i < 8; i++) {
        float x[8];
        unpack2(acc[i][0], x[0], x[1]); unpack2(acc[i][1], x[2], x[3]);
        unpack2(acc[i][2], x[4], x[5]); unpack2(acc[i][3], x[6], x[7]);
        #pragma unroll
        for (int j = 0; j < 8; j++) x[j] += bcol[j];
        float mx = x[0];
        #pragma unroll
        for (int j = 1; j < 8; j++) mx = fmaxf(mx, x[j]);
        #pragma unroll
        for (int o = 1; o < 16; o <<= 1) mx = fmaxf(mx, __shfl_xor_sync(0xffffffffu, mx, o));
        float s = 0.f;
        #pragma unroll
        for (int j = 0; j < 8; j++) { x[j] = __expf(x[j] - mx); s += x[j]; }
        #pragma unroll
        for (int o = 1; o < 16; o <<= 1) s += __shfl_xor_sync(0xffffffffu, s, o);
        float inv = 1.0f / s;
        #pragma unroll
        for (int j = 0; j < 8; j++) x[j] *= inv;

        if (mm[i] >= 0) {
            if (mm[i] != cur) {
                if (cur >= 0) {
                    #pragma unroll
                    for (int j = 0; j < 8; j++)
                        atomicAdd(&fp[(size_t)cur * 128 + tx * 8 + j], run[j]);
                }
                cur = mm[i];
                #pragma unroll
                for (int j = 0; j < 8; j++) run[j] = x[j];
            } else {
                #pragma unroll
                for (int j = 0; j < 8; j++) run[j] += x[j];
            }
        }
    }
    if (cur >= 0) {
        #pragma unroll
        for (int j = 0; j < 8; j++)
            atomicAdd(&fp[(size_t)cur * 128 + tx * 8 + j], run[j]);
    }
}

// ---------------- launch ----------------
extern "C" void kernel_launch(void* const* d_in, const int* in_sizes, int n_in,
                              void* d_out, int out_size) {
    const float *atom, *bond, *W0, *b0, *W1, *b1, *W2, *b2;
    const float *c1sW, *c1b, *c1d1, *c1d2, *c1d3, *c1d4;
    const float *c2sW, *c2b, *c2d1, *c2d2, *c2d3, *c2d4;
    const int *a1, *a2, *a3, *a4, *e1, *e2, *e3, *e4, *mol;

    if (in_sizes[0] == 12800000) {
        atom = (const float*)d_in[0];
        bond = (const float*)d_in[1];
        if (in_sizes[2] == 8192) {
            W0 = (const float*)d_in[2];  b0 = (const float*)d_in[3];
            W1 = (const float*)d_in[4];  b1 = (const float*)d_in[5];
            W2 = (const float*)d_in[6];  b2 = (const float*)d_in[7];
            c1sW = (const float*)d_in[8];  c1b = (const float*)d_in[9];
            c1d1 = (const float*)d_in[10]; c1d2 = (const float*)d_in[11];
            c1d3 = (const float*)d_in[12]; c1d4 = (const float*)d_in[13];
            c2sW = (const float*)d_in[14]; c2b = (const float*)d_in[15];
            c2d1 = (const float*)d_in[16]; c2d2 = (const float*)d_in[17];
            c2d3 = (const float*)d_in[18]; c2d4 = (const float*)d_in[19];
            a1 = (const int*)d_in[20]; a2 = (const int*)d_in[21];
            a3 = (const int*)d_in[22]; a4 = (const int*)d_in[23];
            e1 = (const int*)d_in[24]; e2 = (const int*)d_in[25];
            e3 = (const int*)d_in[26]; e4 = (const int*)d_in[27];
            mol = (const int*)d_in[28];
        } else if (in_sizes[3] == 50000) {
            a1 = (const int*)d_in[2];  e1 = (const int*)d_in[3];
            a2 = (const int*)d_in[4];  e2 = (const int*)d_in[5];
            a3 = (const int*)d_in[6];  e3 = (const int*)d_in[7];
            a4 = (const int*)d_in[8];  e4 = (const int*)d_in[9];
            mol = (const int*)d_in[10];
            W0 = (const float*)d_in[11]; b0 = (const float*)d_in[12];
            W1 = (const float*)d_in[13]; b1 = (const float*)d_in[14];
            W2 = (const float*)d_in[15]; b2 = (const float*)d_in[16];
            c1sW = (const float*)d_in[17]; c1b = (const float*)d_in[18];
            c1d1 = (const float*)d_in[19]; c1d2 = (const float*)d_in[20];
            c1d3 = (const float*)d_in[21]; c1d4 = (const float*)d_in[22];
            c2sW = (const float*)d_in[23]; c2b = (const float*)d_in[24];
            c2d1 = (const float*)d_in[25]; c2d2 = (const float*)d_in[26];
            c2d3 = (const float*)d_in[27]; c2d4 = (const float*)d_in[28];
        } else {
            a1 = (const int*)d_in[2];  a2 = (const int*)d_in[3];
            a3 = (const int*)d_in[4];  a4 = (const int*)d_in[5];
            e1 = (const int*)d_in[6];  e2 = (const int*)d_in[7];
            e3 = (const int*)d_in[8];  e4 = (const int*)d_in[9];
            mol = (const int*)d_in[10];
            W0 = (const float*)d_in[11]; b0 = (const float*)d_in[12];
            W1 = (const float*)d_in[13]; b1 = (const float*)d_in[14];
            W2 = (const float*)d_in[15]; b2 = (const float*)d_in[16];
            c1sW = (const float*)d_in[17]; c1b = (const float*)d_in[18];
            c1d1 = (const float*)d_in[19]; c1d2 = (const float*)d_in[20];
            c1d3 = (const float*)d_in[21]; c1d4 = (const float*)d_in[22];
            c2sW = (const float*)d_in[23]; c2b = (const float*)d_in[24];
            c2d1 = (const float*)d_in[25]; c2d2 = (const float*)d_in[26];
            c2d3 = (const float*)d_in[27]; c2d4 = (const float*)d_in[28];
        }
    } else {
        a1 = (const int*)d_in[0];  a2 = (const int*)d_in[1];
        a3 = (const int*)d_in[2];  a4 = (const int*)d_in[3];
        atom = (const float*)d_in[4];
        e1 = (const int*)d_in[5];  e2 = (const int*)d_in[6];
        e3 = (const int*)d_in[7];  e4 = (const int*)d_in[8];
        bond = (const float*)d_in[9];
        c1b = (const float*)d_in[10];
        c1d1 = (const float*)d_in[11]; c1d2 = (const float*)d_in[12];
        c1d3 = (const float*)d_in[13]; c1d4 = (const float*)d_in[14];
        c1sW = (const float*)d_in[15];
        c2b = (const float*)d_in[16];
        c2d1 = (const float*)d_in[17]; c2d2 = (const float*)d_in[18];
        c2d3 = (const float*)d_in[19]; c2d4 = (const float*)d_in[20];
        c2sW = (const float*)d_in[21];
        mol = (const int*)d_in[22];
        if (in_sizes[24] == 128) {
            W0 = (const float*)d_in[23]; b0 = (const float*)d_in[24];
            W1 = (const float*)d_in[25]; b1 = (const float*)d_in[26];
            W2 = (const float*)d_in[27]; b2 = (const float*)d_in[28];
        } else {
            W0 = (const float*)d_in[23]; W1 = (const float*)d_in[24];
            W2 = (const float*)d_in[25];
            b0 = (const float*)d_in[26]; b1 = (const float*)d_in[27];
            b2 = (const float*)d_in[28];
        }
    }

    float* fp = (float*)d_out;

    float *Hp, *Xp;
    cudaGetSymbolAddress((void**)&Hp, g_H);
    cudaGetSymbolAddress((void**)&Xp, g_X);

    cudaFuncSetAttribute(conv_kernel<64>,  cudaFuncAttributeMaxDynamicSharedMemorySize, CONV_SMEM);
    cudaFuncSetAttribute(conv_kernel<128>, cudaFuncAttributeMaxDynamicSharedMemorySize, CONV_SMEM);
    cudaFuncSetAttribute((const void*)fp_kernel<64, false>,  cudaFuncAttributeMaxDynamicSharedMemorySize, FP_SMEM);
    cudaFuncSetAttribute((const void*)fp_kernel<128, true>,  cudaFuncAttributeMaxDynamicSharedMemorySize, FP_SMEM);

    cudaMemsetAsync(d_out, 0, (size_t)out_size * sizeof(float));
    zero_stats_kernel<<<1, 512>>>();

    // fp += segsum(softmax(atom @ W0 + b0))
    fp_kernel<64, false><<<FPB, 256, FP_SMEM>>>(atom, W0, b0, mol, fp, 0);

    // layer 1: gather (raw atom), conv -> g_H (pre-BN) + stats, prep BN consts
    {
        long long total = (long long)NA * 36;
        int gblocks = (int)((total + 255) / 256);
        gather_kernel<64, false><<<gblocks, 256>>>(atom, bond, a1, a2, a3, a4, e1, e2, e3, e4, 0);
    }
    conv_kernel<64><<<4 * TPD, 256, CONV_SMEM>>>(c1sW, c1d1, c1d2, c1d3, c1d4, c1b, Hp, 0);
    prep_stats_kernel<<<1, 128>>>(0, 0);

    // fp += segsum(softmax(bn_relu(H) @ W1 + b1))   (BN fused into fp)
    fp_kernel<128, true><<<FPB, 256, FP_SMEM>>>(Hp, W1, b1, mol, fp, 0);

    // layer 2: gather with fused BN+relu on H, conv -> g_X + stats, prep BN consts
    {
        long long total = (long long)NA * 68;
        int gblocks = (int)((total + 255) / 256);
        gather_kernel<128, true><<<gblocks, 256>>>(Hp, bond, a1, a2, a3, a4, e1, e2, e3, e4, 0);
    }
    conv_kernel<128><<<4 * TPD, 256, CONV_SMEM>>>(c2sW, c2d1, c2d2, c2d3, c2d4, c2b, Xp, 256);
    prep_stats_kernel<<<1, 128>>>(256, 128);

    // fp += segsum(softmax(bn_relu(X) @ W2 + b2))
    fp_kernel<128, true><<<FPB, 256, FP_SMEM>>>(Xp, W2, b2, mol, fp, 128);
}

// round 6
// speedup vs baseline: 1.2788x; 1.2788x over previous
#include <cuda_runtime.h>

#define NA 200000
#define NDG 50000
#define NB 8192
#define EPSBN 1e-5f
#define TPD 391           // row tiles per degree = ceil(50000/128)
#define FPB 1563          // fp blocks = ceil(200000/128)
#define ARS 132           // padded smem row stride (floats); 132*4=528 = 16B-aligned

typedef unsigned long long u64;

__device__ __forceinline__ u64 pack2(float lo, float hi) {
    u64 r; asm("mov.b64 %0, {%1, %2};" : "=l"(r) : "f"(lo), "f"(hi)); return r;
}
__device__ __forceinline__ void unpack2(u64 v, float& lo, float& hi) {
    asm("mov.b64 {%0, %1}, %2;" : "=f"(lo), "=f"(hi) : "l"(v));
}
__device__ __forceinline__ u64 ffma2(u64 a, u64 b, u64 c) {
    u64 d; asm("fma.rn.f32x2 %0, %1, %2, %3;" : "=l"(d) : "l"(a), "l"(b), "l"(c)); return d;
}

// ---------------- scratch ----------------
__device__ float g_G[(size_t)NA * 272];
__device__ float g_H[(size_t)NA * 128];
__device__ float g_X[(size_t)NA * 128];
__device__ float g_stats[512];
__device__ float g_sc[256];
__device__ float g_sh[256];

__global__ void zero_stats_kernel() {
    int i = threadIdx.x;
    if (i < 512) g_stats[i] = 0.f;
}

__global__ void prep_stats_kernel(int statsOff, int scOff) {
    int j = threadIdx.x;
    float mean = g_stats[statsOff + j] * (1.f / NA);
    float var  = g_stats[statsOff + 128 + j] * (1.f / NA) - mean * mean;
    float r = rsqrtf(var + EPSBN);
    g_sc[scOff + j] = r;
    g_sh[scOff + j] = -mean * r;
}

// ---------------- gather (BN+relu optionally fused on atom features) ----------------
template <int KIN, bool NORM>
__global__ void gather_kernel(const float* __restrict__ Hin,
                              const float* __restrict__ bond,
                              const int* __restrict__ a1, const int* __restrict__ a2,
                              const int* __restrict__ a3, const int* __restrict__ a4,
                              const int* __restrict__ b1, const int* __restrict__ b2,
                              const int* __restrict__ b3, const int* __restrict__ b4,
                              int scOff) {
    constexpr int CK  = 2 * KIN + 16;
    constexpr int CK4 = CK / 4;
    long long idx = (long long)blockIdx.x * blockDim.x + threadIdx.x;
    if (idx >= (long long)NA * CK4) return;
    int row = (int)(idx / CK4);
    int c4  = (int)(idx - (long long)row * CK4);
    int d   = row / NDG;
    int r   = row - d * NDG;
    int deg = d + 1;
    const int* aidx; const int* bidx;
    if (d == 0)      { aidx = a1; bidx = b1; }
    else if (d == 1) { aidx = a2; bidx = b2; }
    else if (d == 2) { aidx = a3; bidx = b3; }
    else             { aidx = a4; bidx = b4; }
    int c = c4 * 4;
    float4 out;
    if (c < KIN) {
        float4 v = *(const float4*)(Hin + (size_t)row * KIN + c);
        if (NORM) {
            float4 sc4 = *(const float4*)&g_sc[scOff + c];
            float4 sh4 = *(const float4*)&g_sh[scOff + c];
            v.x = fmaxf(0.f, fmaf(v.x, sc4.x, sh4.x));
            v.y = fmaxf(0.f, fmaf(v.y, sc4.y, sh4.y));
            v.z = fmaxf(0.f, fmaf(v.z, sc4.z, sh4.z));
            v.w = fmaxf(0.f, fmaf(v.w, sc4.w, sh4.w));
        }
        out = v;
    } else if (c < 2 * KIN) {
        int cc = c - KIN;
        float4 sc4, sh4;
        if (NORM) {
            sc4 = *(const float4*)&g_sc[scOff + cc];
            sh4 = *(const float4*)&g_sh[scOff + cc];
        }
        float4 s = make_float4(0.f, 0.f, 0.f, 0.f);
        #pragma unroll 4
        for (int t = 0; t < deg; t++) {
            int nb = aidx[r * deg + t];
            float4 v = *(const float4*)(Hin + (size_t)nb * KIN + cc);
            if (NORM) {
                v.x = fmaxf(0.f, fmaf(v.x, sc4.x, sh4.x));
                v.y = fmaxf(0.f, fmaf(v.y, sc4.y, sh4.y));
                v.z = fmaxf(0.f, fmaf(v.z, sc4.z, sh4.z));
                v.w = fmaxf(0.f, fmaf(v.w, sc4.w, sh4.w));
            }
            s.x += v.x; s.y += v.y; s.z += v.z; s.w += v.w;
        }
        out = s;
    } else {
        int cc = c - 2 * KIN;
        float4 s = make_float4(0.f, 0.f, 0.f, 0.f);
        #pragma unroll 4
        for (int t = 0; t < deg; t++) {
            int nb = bidx[r * deg + t];
            float4 v = *(const float4*)(bond + (size_t)nb * 16 + cc);
            s.x += v.x; s.y += v.y; s.z += v.z; s.w += v.w;
        }
        out = s;
    }
    *(float4*)(g_G + (size_t)row * CK + c) = out;
}

// ---------------- GEMM core: As[k][row] (k-major), Ws[k][col], row-pair FFMA2 ----------------
// thread tile: 16 rows (ty*16..+15) x 8 cols (tx*8..+7); acc[rowpair][col] u64
__device__ __forceinline__ void sts_chunk(float* As, float* Ws, int tid,
                                          const float4 a[4], const float4 w[4]) {
    #pragma unroll
    for (int q = 0; q < 4; q++) {
        As[(q * 4 + 0) * ARS + tid] = a[q].x;
        As[(q * 4 + 1) * ARS + tid] = a[q].y;
        As[(q * 4 + 2) * ARS + tid] = a[q].z;
        As[(q * 4 + 3) * ARS + tid] = a[q].w;
        int i = tid + q * 128;
        *(float4*)&Ws[(i >> 5) * ARS + (i & 31) * 4] = w[q];
    }
}

__device__ __forceinline__ void compute_chunk(const float* As, const float* Ws,
                                              int tx, int ty, u64 acc[8][8]) {
    #pragma unroll 4
    for (int k = 0; k < 16; k++) {
        float4 w0 = *(const float4*)&Ws[k * ARS + tx * 8];
        float4 w1 = *(const float4*)&Ws[k * ARS + tx * 8 + 4];
        u64 wd[8];
        wd[0] = pack2(w0.x, w0.x); wd[1] = pack2(w0.y, w0.y);
        wd[2] = pack2(w0.z, w0.z); wd[3] = pack2(w0.w, w0.w);
        wd[4] = pack2(w1.x, w1.x); wd[5] = pack2(w1.y, w1.y);
        wd[6] = pack2(w1.z, w1.z); wd[7] = pack2(w1.w, w1.w);
        ulonglong2 A0 = *(const ulonglong2*)&As[k * ARS + ty * 16];
        ulonglong2 A1 = *(const ulonglong2*)&As[k * ARS + ty * 16 + 4];
        ulonglong2 A2 = *(const ulonglong2*)&As[k * ARS + ty * 16 + 8];
        ulonglong2 A3 = *(const ulonglong2*)&As[k * ARS + ty * 16 + 12];
        u64 ap[8] = {A0.x, A0.y, A1.x, A1.y, A2.x, A2.y, A3.x, A3.y};
        #pragma unroll
        for (int rp = 0; rp < 8; rp++) {
            #pragma unroll
            for (int j = 0; j < 8; j++)
                acc[rp][j] = ffma2(ap[rp], wd[j], acc[rp][j]);
        }
    }
}

// ---------------- conv GEMM ----------------
template <int KIN>
__global__ __launch_bounds__(128, 2)
void conv_kernel(const float* __restrict__ selfW,
                 const float* __restrict__ dW1, const float* __restrict__ dW2,
                 const float* __restrict__ dW3, const float* __restrict__ dW4,
                 const float* __restrict__ bias,
                 float* __restrict__ Xout, int statsOff) {
    constexpr int CK  = 2 * KIN + 16;
    constexpr int NCH = CK / 16;
    __shared__ alignas(16) float As2[2][16 * ARS];
    __shared__ alignas(16) float Ws2[2][16 * ARS];

    int tid = threadIdx.x;
    int tx = tid & 15, ty = tid >> 4;
    int d    = blockIdx.x / TPD;
    int tile = blockIdx.x - d * TPD;
    int rowbase = d * NDG + tile * 128;
    int rowend  = min((d + 1) * NDG, rowbase + 128);
    const float* dW = (d == 0) ? dW1 : (d == 1) ? dW2 : (d == 2) ? dW3 : dW4;

    int rg = rowbase + tid;
    bool rvalid = rg < rowend;
    const float* Grow = g_G + (size_t)rg * CK;

    float bcol[8];
    *(float4*)&bcol[0] = *(const float4*)&bias[tx * 8];
    *(float4*)&bcol[4] = *(const float4*)&bias[tx * 8 + 4];

    float4 a[4], w[4];
    #pragma unroll
    for (int q = 0; q < 4; q++) {
        a[q] = rvalid ? *(const float4*)(Grow + 4 * q) : make_float4(0,0,0,0);
        w[q] = ((const float4*)selfW)[tid + q * 128];
    }
    sts_chunk(As2[0], Ws2[0], tid, a, w);
    __syncthreads();

    u64 acc[8][8];
    #pragma unroll
    for (int rp = 0; rp < 8; rp++)
        #pragma unroll
        for (int j = 0; j < 8; j++) acc[rp][j] = 0ull;

    for (int c = 0; c < NCH; c++) {
        int buf = c & 1;
        bool havenext = (c + 1 < NCH);
        if (havenext) {
            int k0 = (c + 1) * 16;
            const float* wsrc = (k0 < KIN) ? (selfW + (size_t)k0 * 128)
                                           : (dW + (size_t)(k0 - KIN) * 128);
            #pragma unroll
            for (int q = 0; q < 4; q++) {
                a[q] = rvalid ? *(const float4*)(Grow + k0 + 4 * q) : make_float4(0,0,0,0);
                w[q] = ((const float4*)wsrc)[tid + q * 128];
            }
        }
        compute_chunk(As2[buf], Ws2[buf], tx, ty, acc);
        if (havenext) sts_chunk(As2[buf ^ 1], Ws2[buf ^ 1], tid, a, w);
        __syncthreads();
    }

    // epilogue
    float psum[8], psq[8];
    #pragma unroll
    for (int j = 0; j < 8; j++) { psum[j] = 0.f; psq[j] = 0.f; }
    #pragma unroll
    for (int rp = 0; rp < 8; rp++) {
        float xe[8], xo[8];
        #pragma unroll
        for (int j = 0; j < 8; j++) {
            unpack2(acc[rp][j], xe[j], xo[j]);
            xe[j] += bcol[j]; xo[j] += bcol[j];
        }
        int re = rowbase + ty * 16 + 2 * rp;
        if (re < rowend) {
            float* outp = Xout + (size_t)re * 128 + tx * 8;
            *(float4*)outp       = make_float4(xe[0], xe[1], xe[2], xe[3]);
            *(float4*)(outp + 4) = make_float4(xe[4], xe[5], xe[6], xe[7]);
            #pragma unroll
            for (int j = 0; j < 8; j++) { psum[j] += xe[j]; psq[j] += xe[j] * xe[j]; }
        }
        if (re + 1 < rowend) {
            float* outp = Xout + (size_t)(re + 1) * 128 + tx * 8;
            *(float4*)outp       = make_float4(xo[0], xo[1], xo[2], xo[3]);
            *(float4*)(outp + 4) = make_float4(xo[4], xo[5], xo[6], xo[7]);
            #pragma unroll
            for (int j = 0; j < 8; j++) { psum[j] += xo[j]; psq[j] += xo[j] * xo[j]; }
        }
    }
    float* redS = &As2[0][0];
    float* redQ = redS + 1024;
    #pragma unroll
    for (int j = 0; j < 8; j++) {
        redS[ty * 128 + tx * 8 + j] = psum[j];
        redQ[ty * 128 + tx * 8 + j] = psq[j];
    }
    __syncthreads();
    if (tid < 128) {
        float s = 0.f, q = 0.f;
        #pragma unroll
        for (int t = 0; t < 8; t++) { s += redS[t * 128 + tid]; q += redQ[t * 128 + tid]; }
        atomicAdd(&g_stats[statsOff + tid], s);
        atomicAdd(&g_stats[statsOff + 128 + tid], q);
    }
}

// ---------------- fp update ----------------
template <int KIN, bool NORM>
__global__ __launch_bounds__(128, 2)
void fp_kernel(const float* __restrict__ Hin,
               const float* __restrict__ W, const float* __restrict__ bias,
               const int* __restrict__ mol_ids,
               float* __restrict__ fp, int scOff) {
    constexpr int NCH = KIN / 16;
    __shared__ alignas(16) float As2[2][16 * ARS];
    __shared__ alignas(16) float Ws2[2][16 * ARS];
    __shared__ float sc_s[128], sh_s[128];

    int tid = threadIdx.x;
    int tx = tid & 15, ty = tid >> 4;
    int rowbase = blockIdx.x * 128;

    int rg = rowbase + tid;
    bool rvalid = rg < NA;
    const float* Hrow = Hin + (size_t)rg * KIN;

    float bcol[8];
    *(float4*)&bcol[0] = *(const float4*)&bias[tx * 8];
    *(float4*)&bcol[4] = *(const float4*)&bias[tx * 8 + 4];

    if (NORM) {
        if (tid < KIN) { sc_s[tid] = g_sc[scOff + tid]; sh_s[tid] = g_sh[scOff + tid]; }
        __syncthreads();
    }

    auto bn4 = [&](float4& v, int c) {
        if (NORM) {
            float4 s4 = *(const float4*)&sc_s[c];
            float4 h4 = *(const float4*)&sh_s[c];
            v.x = fmaxf(0.f, fmaf(v.x, s4.x, h4.x));
            v.y = fmaxf(0.f, fmaf(v.y, s4.y, h4.y));
            v.z = fmaxf(0.f, fmaf(v.z, s4.z, h4.z));
            v.w = fmaxf(0.f, fmaf(v.w, s4.w, h4.w));
        }
    };

    float4 a[4], w[4];
    #pragma unroll
    for (int q = 0; q < 4; q++) {
        a[q] = rvalid ? *(const float4*)(Hrow + 4 * q) : make_float4(0,0,0,0);
        bn4(a[q], 4 * q);
        w[q] = ((const float4*)W)[tid + q * 128];
    }
    sts_chunk(As2[0], Ws2[0], tid, a, w);
    __syncthreads();

    u64 acc[8][8];
    #pragma unroll
    for (int rp = 0; rp < 8; rp++)
        #pragma unroll
        for (int j = 0; j < 8; j++) acc[rp][j] = 0ull;

    for (int c = 0; c < NCH; c++) {
        int buf = c & 1;
        bool havenext = (c + 1 < NCH);
        if (havenext) {
            int k0 = (c + 1) * 16;
            const float* wsrc = W + (size_t)k0 * 128;
            #pragma unroll
            for (int q = 0; q < 4; q++) {
                a[q] = rvalid ? *(const float4*)(Hrow + k0 + 4 * q) : make_float4(0,0,0,0);
                bn4(a[q], k0 + 4 * q);
                w[q] = ((const float4*)wsrc)[tid + q * 128];
            }
        }
        compute_chunk(As2[buf], Ws2[buf], tx, ty, acc);
        if (havenext) sts_chunk(As2[buf ^ 1], Ws2[buf ^ 1], tid, a, w);
        __syncthreads();
    }

    // mol ids for this thread's 16 rows
    int mm[16];
    #pragma unroll
    for (int i = 0; i < 16; i++) {
        int r = rowbase + ty * 16 + i;
        mm[i] = (r < NA) ? mol_ids[r] : -1;
    }

    int cur = -1;
    float run[8];
    #pragma unroll
    for (int rp = 0; rp < 8; rp++) {
        float xr[2][8];
        #pragma unroll
        for (int j = 0; j < 8; j++) {
            unpack2(acc[rp][j], xr[0][j], xr[1][j]);
            xr[0][j] += bcol[j]; xr[1][j] += bcol[j];
        }
        #pragma unroll
        for (int h = 0; h < 2; h++) {
            float* x = xr[h];
            // softmax across 128 cols: 8 local + 16-lane butterfly
            float mx = x[0];
            #pragma unroll
            for (int j = 1; j < 8; j++) mx = fmaxf(mx, x[j]);
            #pragma unroll
            for (int o = 1; o < 16; o <<= 1) mx = fmaxf(mx, __shfl_xor_sync(0xffffffffu, mx, o));
            float s = 0.f;
            #pragma unroll
            for (int j = 0; j < 8; j++) { x[j] = __expf(x[j] - mx); s += x[j]; }
            #pragma unroll
            for (int o = 1; o < 16; o <<= 1) s += __shfl_xor_sync(0xffffffffu, s, o);
            float inv = 1.0f / s;
            #pragma unroll
            for (int j = 0; j < 8; j++) x[j] *= inv;

            int i = 2 * rp + h;
            if (mm[i] >= 0) {
                if (mm[i] != cur) {
                    if (cur >= 0) {
                        #pragma unroll
                        for (int j = 0; j < 8; j++)
                            atomicAdd(&fp[(size_t)cur * 128 + tx * 8 + j], run[j]);
                    }
                    cur = mm[i];
                    #pragma unroll
                    for (int j = 0; j < 8; j++) run[j] = x[j];
                } else {
                    #pragma unroll
                    for (int j = 0; j < 8; j++) run[j] += x[j];
                }
            }
        }
    }
    if (cur >= 0) {
        #pragma unroll
        for (int j = 0; j < 8; j++)
            atomicAdd(&fp[(size_t)cur * 128 + tx * 8 + j], run[j]);
    }
}

// ---------------- launch ----------------
extern "C" void kernel_launch(void* const* d_in, const int* in_sizes, int n_in,
                              void* d_out, int out_size) {
    const float *atom, *bond, *W0, *b0, *W1, *b1, *W2, *b2;
    const float *c1sW, *c1b, *c1d1, *c1d2, *c1d3, *c1d4;
    const float *c2sW, *c2b, *c2d1, *c2d2, *c2d3, *c2d4;
    const int *a1, *a2, *a3, *a4, *e1, *e2, *e3, *e4, *mol;

    if (in_sizes[0] == 12800000) {
        atom = (const float*)d_in[0];
        bond = (const float*)d_in[1];
        if (in_sizes[2] == 8192) {
            W0 = (const float*)d_in[2];  b0 = (const float*)d_in[3];
            W1 = (const float*)d_in[4];  b1 = (const float*)d_in[5];
            W2 = (const float*)d_in[6];  b2 = (const float*)d_in[7];
            c1sW = (const float*)d_in[8];  c1b = (const float*)d_in[9];
            c1d1 = (const float*)d_in[10]; c1d2 = (const float*)d_in[11];
            c1d3 = (const float*)d_in[12]; c1d4 = (const float*)d_in[13];
            c2sW = (const float*)d_in[14]; c2b = (const float*)d_in[15];
            c2d1 = (const float*)d_in[16]; c2d2 = (const float*)d_in[17];
            c2d3 = (const float*)d_in[18]; c2d4 = (const float*)d_in[19];
            a1 = (const int*)d_in[20]; a2 = (const int*)d_in[21];
            a3 = (const int*)d_in[22]; a4 = (const int*)d_in[23];
            e1 = (const int*)d_in[24]; e2 = (const int*)d_in[25];
            e3 = (const int*)d_in[26]; e4 = (const int*)d_in[27];
            mol = (const int*)d_in[28];
        } else if (in_sizes[3] == 50000) {
            a1 = (const int*)d_in[2];  e1 = (const int*)d_in[3];
            a2 = (const int*)d_in[4];  e2 = (const int*)d_in[5];
            a3 = (const int*)d_in[6];  e3 = (const int*)d_in[7];
            a4 = (const int*)d_in[8];  e4 = (const int*)d_in[9];
            mol = (const int*)d_in[10];
            W0 = (const float*)d_in[11]; b0 = (const float*)d_in[12];
            W1 = (const float*)d_in[13]; b1 = (const float*)d_in[14];
            W2 = (const float*)d_in[15]; b2 = (const float*)d_in[16];
            c1sW = (const float*)d_in[17]; c1b = (const float*)d_in[18];
            c1d1 = (const float*)d_in[19]; c1d2 = (const float*)d_in[20];
            c1d3 = (const float*)d_in[21]; c1d4 = (const float*)d_in[22];
            c2sW = (const float*)d_in[23]; c2b = (const float*)d_in[24];
            c2d1 = (const float*)d_in[25]; c2d2 = (const float*)d_in[26];
            c2d3 = (const float*)d_in[27]; c2d4 = (const float*)d_in[28];
        } else {
            a1 = (const int*)d_in[2];  a2 = (const int*)d_in[3];
            a3 = (const int*)d_in[4];  a4 = (const int*)d_in[5];
            e1 = (const int*)d_in[6];  e2 = (const int*)d_in[7];
            e3 = (const int*)d_in[8];  e4 = (const int*)d_in[9];
            mol = (const int*)d_in[10];
            W0 = (const float*)d_in[11]; b0 = (const float*)d_in[12];
            W1 = (const float*)d_in[13]; b1 = (const float*)d_in[14];
            W2 = (const float*)d_in[15]; b2 = (const float*)d_in[16];
            c1sW = (const float*)d_in[17]; c1b = (const float*)d_in[18];
            c1d1 = (const float*)d_in[19]; c1d2 = (const float*)d_in[20];
            c1d3 = (const float*)d_in[21]; c1d4 = (const float*)d_in[22];
            c2sW = (const float*)d_in[23]; c2b = (const float*)d_in[24];
            c2d1 = (const float*)d_in[25]; c2d2 = (const float*)d_in[26];
            c2d3 = (const float*)d_in[27]; c2d4 = (const float*)d_in[28];
        }
    } else {
        a1 = (const int*)d_in[0];  a2 = (const int*)d_in[1];
        a3 = (const int*)d_in[2];  a4 = (const int*)d_in[3];
        atom = (const float*)d_in[4];
        e1 = (const int*)d_in[5];  e2 = (const int*)d_in[6];
        e3 = (const int*)d_in[7];  e4 = (const int*)d_in[8];
        bond = (const float*)d_in[9];
        c1b = (const float*)d_in[10];
        c1d1 = (const float*)d_in[11]; c1d2 = (const float*)d_in[12];
        c1d3 = (const float*)d_in[13]; c1d4 = (const float*)d_in[14];
        c1sW = (const float*)d_in[15];
        c2b = (const float*)d_in[16];
        c2d1 = (const float*)d_in[17]; c2d2 = (const float*)d_in[18];
        c2d3 = (const float*)d_in[19]; c2d4 = (const float*)d_in[20];
        c2sW = (const float*)d_in[21];
        mol = (const int*)d_in[22];
        if (in_sizes[24] == 128) {
            W0 = (const float*)d_in[23]; b0 = (const float*)d_in[24];
            W1 = (const float*)d_in[25]; b1 = (const float*)d_in[26];
            W2 = (const float*)d_in[27]; b2 = (const float*)d_in[28];
        } else {
            W0 = (const float*)d_in[23]; W1 = (const float*)d_in[24];
            W2 = (const float*)d_in[25];
            b0 = (const float*)d_in[26]; b1 = (const float*)d_in[27];
            b2 = (const float*)d_in[28];
        }
    }

    float* fp = (float*)d_out;

    float *Hp, *Xp;
    cudaGetSymbolAddress((void**)&Hp, g_H);
    cudaGetSymbolAddress((void**)&Xp, g_X);

    cudaMemsetAsync(d_out, 0, (size_t)out_size * sizeof(float));
    zero_stats_kernel<<<1, 512>>>();

    // fp += segsum(softmax(atom @ W0 + b0))
    fp_kernel<64, false><<<FPB, 128>>>(atom, W0, b0, mol, fp, 0);

    // layer 1: gather (raw atom), conv -> g_H (pre-BN) + stats, prep BN consts
    {
        long long total = (long long)NA * 36;
        int gblocks = (int)((total + 255) / 256);
        gather_kernel<64, false><<<gblocks, 256>>>(atom, bond, a1, a2, a3, a4, e1, e2, e3, e4, 0);
    }
    conv_kernel<64><<<4 * TPD, 128>>>(c1sW, c1d1, c1d2, c1d3, c1d4, c1b, Hp, 0);
    prep_stats_kernel<<<1, 128>>>(0, 0);

    // fp += segsum(softmax(bn_relu(H) @ W1 + b1))
    fp_kernel<128, true><<<FPB, 128>>>(Hp, W1, b1, mol, fp, 0);

    // layer 2: gather with fused BN+relu on H, conv -> g_X + stats, prep BN consts
    {
        long long total = (long long)NA * 68;
        int gblocks = (int)((total + 255) / 256);
        gather_kernel<128, true><<<gblocks, 256>>>(Hp, bond, a1, a2, a3, a4, e1, e2, e3, e4, 0);
    }
    conv_kernel<128><<<4 * TPD, 128>>>(c2sW, c2d1, c2d2, c2d3, c2d4, c2b, Xp, 256);
    prep_stats_kernel<<<1, 128>>>(256, 128);

    // fp += segsum(softmax(bn_relu(X) @ W2 + b2))
    fp_kernel<128, true><<<FPB, 128>>>(Xp, W2, b2, mol, fp, 128);
}